// round 10
// baseline (speedup 1.0000x reference)
#include <cuda_runtime.h>
#include <cuda_bf16.h>

#define N_CTRL 64
#define N_EVAL 2001
#define DEG 3
#define INV_INTERNAL (1.0f / 61.0f)   // internal knots at k/61

#define TPB 256
#define U_TILE 8
#define VSPLIT 2
#define VCHUNK 1001                   // ceil(2001/2)
#define KITER 4                       // ceil(VCHUNK / TPB)

__device__ __forceinline__ float knotf(int j) {
    if (j <= DEG) return 0.0f;
    if (j >= N_CTRL) return 1.0f;
    return (float)(j - DEG) * INV_INTERNAL;
}

// span = clip(searchsorted(knots, t, 'right') - 1, p, n_ctrl-1), analytic
__device__ __forceinline__ int find_span(float t) {
    int k = (int)floorf(t * 61.0f);
    if (k < 0) k = 0;
    if (k > 60) k = 60;
    if (k < 60 && (float)(k + 1) * INV_INTERNAL <= t) ++k;
    if (k > 0  && (float)k * INV_INTERNAL > t)        --k;
    return DEG + k;
}

// Cox-de-Boor (NURBS book A2.2), p=3. FAST=1 uses __fdividef.
template <int FAST>
__device__ __forceinline__ void basis_funcs(float u, int span, float N[4]) {
    float left[4], right[4];
    N[0] = 1.0f;
    #pragma unroll
    for (int j = 1; j <= DEG; ++j) {
        left[j]  = u - knotf(span + 1 - j);
        right[j] = knotf(span + j) - u;
        float saved = 0.0f;
        #pragma unroll
        for (int r = 0; r < j; ++r) {
            float denom = right[r + 1] + left[j - r];
            float temp  = FAST ? __fdividef(N[r], denom) : (N[r] / denom);
            N[r] = saved + right[r + 1] * temp;
            saved = left[j - r] * temp;
        }
        N[j] = saved;
    }
}

// v-basis: closed-form uniform cubic for interior spans (knots j in [3,64]
// are exactly (j-3)/61, so spans 5..61 see purely uniform knots), generic
// Cox-de-Boor fallback at the clamped ends.
__device__ __forceinline__ void basis_v(float v, int span, float B[4]) {
    if (span >= 5 && span <= 61) {
        float t  = v * 61.0f - (float)(span - DEG);   // in [0,1)
        float s  = 1.0f - t;
        float t2 = t * t;
        float t3 = t2 * t;
        B[0] = s * s * s * (1.0f / 6.0f);
        B[3] = t3 * (1.0f / 6.0f);
        B[1] = 0.5f * t3 - t2 + (2.0f / 3.0f);
        B[2] = 1.0f - B[0] - B[1] - B[3];             // partition of unity
    } else {
        basis_funcs<1>(v, span, B);
    }
}

// ---------------- single fused kernel ----------------
// Block: 8 u-rows x 1001-v chunk. Prologue u-collapses control points into
// smem (inline exact u-basis); main loop computes v-basis inline (closed form).
__global__ __launch_bounds__(TPB) void nurbs_kernel(const float* __restrict__ cp,
                                                    const float* __restrict__ pu,
                                                    const float* __restrict__ pv,
                                                    float* __restrict__ out) {
    __shared__ float4 s_curve[U_TILE][N_CTRL];   // 8 KB

    const int u0  = blockIdx.y * U_TILE;
    const int tid = threadIdx.x;
    const int nrows  = (N_EVAL - u0) < U_TILE ? (N_EVAL - u0) : U_TILE;
    const int vstart = blockIdx.x * VCHUNK;
    const int vend   = (vstart + VCHUNK) < N_EVAL ? (vstart + VCHUNK) : N_EVAL;

    // ---- prologue: inline u-basis + u-collapse; 512 items, 2 per thread ----
    #pragma unroll
    for (int it = 0; it < 2; ++it) {
        const int item = tid + it * TPB;
        const int r = item >> 6;      // 0..7
        const int j = item & 63;      // 0..63
        if (r < nrows) {
            const float uu = pu[u0 + r];          // broadcast within 64-lane group
            const int   su = find_span(uu);
            float B[4];
            basis_funcs<0>(uu, su, B);            // exact division (per block)
            const float* base = cp + ((su - DEG) * N_CTRL + j) * 3;
            float cx = 0.f, cy = 0.f, cz = 0.f;
            #pragma unroll
            for (int a = 0; a < 4; ++a) {
                const float* q = base + a * (N_CTRL * 3);
                cx += B[a] * q[0];
                cy += B[a] * q[1];
                cz += B[a] * q[2];
            }
            s_curve[r][j] = make_float4(cx, cy, cz, 0.f);
        }
    }
    __syncthreads();

    // ---- batched pv loads: independent LDGs in flight ----
    float pvv[KITER];
    #pragma unroll
    for (int k = 0; k < KITER; ++k) {
        int p  = vstart + k * TPB + tid;
        int pc = p < vend ? p : vend - 1;
        pvv[k] = pv[pc];
    }

    // ---- main: closed-form v-basis, 8 rows per point, direct stores ----
    #pragma unroll
    for (int k = 0; k < KITER; ++k) {
        const int p = vstart + k * TPB + tid;
        if (p < vend) {
            const int sv = find_span(pvv[k]);
            float B[4];
            basis_v(pvv[k], sv, B);
            const int o = sv - DEG;
            #pragma unroll
            for (int r = 0; r < U_TILE; ++r) {
                if (r < nrows) {
                    const float4 c0 = s_curve[r][o + 0];
                    const float4 c1 = s_curve[r][o + 1];
                    const float4 c2 = s_curve[r][o + 2];
                    const float4 c3 = s_curve[r][o + 3];
                    float x = B[0] * c0.x + B[1] * c1.x + B[2] * c2.x + B[3] * c3.x;
                    float y = B[0] * c0.y + B[1] * c1.y + B[2] * c2.y + B[3] * c3.y;
                    float z = B[0] * c0.z + B[1] * c1.z + B[2] * c2.z + B[3] * c3.z;
                    float* dst = out + ((size_t)(u0 + r) * N_EVAL + p) * 3;
                    dst[0] = x;
                    dst[1] = y;
                    dst[2] = z;
                }
            }
        }
    }
}

extern "C" void kernel_launch(void* const* d_in, const int* in_sizes, int n_in,
                              void* d_out, int out_size) {
    const float* cp = (const float*)d_in[0];   // [64,64,3]
    const float* pu = (const float*)d_in[1];   // [2001]
    const float* pv = (const float*)d_in[2];   // [2001]
    float* out = (float*)d_out;

    dim3 grid(VSPLIT, (N_EVAL + U_TILE - 1) / U_TILE);   // (2, 251)
    nurbs_kernel<<<grid, TPB>>>(cp, pu, pv, out);
}

// round 11
// speedup vs baseline: 1.1189x; 1.1189x over previous
#include <cuda_runtime.h>
#include <cuda_bf16.h>

#define N_CTRL 64
#define N_EVAL 2001
#define DEG 3
#define INV_INTERNAL (1.0f / 61.0f)   // internal knots at k/61

#define TPB 256
#define U_TILE 8
#define VSPLIT 4
#define VCHUNK 501                    // ceil(2001/4)
#define KITER 2                       // ceil(VCHUNK / TPB)

__device__ __forceinline__ float knotf(int j) {
    if (j <= DEG) return 0.0f;
    if (j >= N_CTRL) return 1.0f;
    return (float)(j - DEG) * INV_INTERNAL;
}

// span = clip(searchsorted(knots, t, 'right') - 1, p, n_ctrl-1), analytic
__device__ __forceinline__ int find_span(float t) {
    int k = (int)floorf(t * 61.0f);
    if (k < 0) k = 0;
    if (k > 60) k = 60;
    if (k < 60 && (float)(k + 1) * INV_INTERNAL <= t) ++k;
    if (k > 0  && (float)k * INV_INTERNAL > t)        --k;
    return DEG + k;
}

// Cox-de-Boor (NURBS book A2.2), p=3. FAST=1 uses __fdividef.
template <int FAST>
__device__ __forceinline__ void basis_funcs(float u, int span, float N[4]) {
    float left[4], right[4];
    N[0] = 1.0f;
    #pragma unroll
    for (int j = 1; j <= DEG; ++j) {
        left[j]  = u - knotf(span + 1 - j);
        right[j] = knotf(span + j) - u;
        float saved = 0.0f;
        #pragma unroll
        for (int r = 0; r < j; ++r) {
            float denom = right[r + 1] + left[j - r];
            float temp  = FAST ? __fdividef(N[r], denom) : (N[r] / denom);
            N[r] = saved + right[r + 1] * temp;
            saved = left[j - r] * temp;
        }
        N[j] = saved;
    }
}

// v-basis: closed-form uniform cubic for interior spans (knots j in [3,64]
// are exactly (j-3)/61, so spans 5..61 see purely uniform knots), generic
// Cox-de-Boor fallback at the clamped ends.
__device__ __forceinline__ void basis_v(float v, int span, float B[4]) {
    if (span >= 5 && span <= 61) {
        float t  = v * 61.0f - (float)(span - DEG);   // in [0,1)
        float s  = 1.0f - t;
        float t2 = t * t;
        float t3 = t2 * t;
        B[0] = s * s * s * (1.0f / 6.0f);
        B[3] = t3 * (1.0f / 6.0f);
        B[1] = 0.5f * t3 - t2 + (2.0f / 3.0f);
        B[2] = 1.0f - B[0] - B[1] - B[3];             // partition of unity
    } else {
        basis_funcs<1>(v, span, B);
    }
}

// ---------------- single fused kernel ----------------
// Block: 8 u-rows x 501-v chunk. Prologue u-collapses control points into
// smem (inline exact u-basis); main loop computes v-basis inline (closed form).
__global__ __launch_bounds__(TPB) void nurbs_kernel(const float* __restrict__ cp,
                                                    const float* __restrict__ pu,
                                                    const float* __restrict__ pv,
                                                    float* __restrict__ out) {
    __shared__ float4 s_curve[U_TILE][N_CTRL];   // 8 KB

    const int u0  = blockIdx.y * U_TILE;
    const int tid = threadIdx.x;
    const int nrows  = (N_EVAL - u0) < U_TILE ? (N_EVAL - u0) : U_TILE;
    const int vstart = blockIdx.x * VCHUNK;
    const int vend   = (vstart + VCHUNK) < N_EVAL ? (vstart + VCHUNK) : N_EVAL;

    // ---- prologue: inline u-basis + u-collapse; 512 items, 2 per thread ----
    #pragma unroll
    for (int it = 0; it < 2; ++it) {
        const int item = tid + it * TPB;
        const int r = item >> 6;      // 0..7
        const int j = item & 63;      // 0..63
        if (r < nrows) {
            const float uu = pu[u0 + r];          // broadcast within 64-lane group
            const int   su = find_span(uu);
            float B[4];
            basis_funcs<0>(uu, su, B);            // exact division (per block)
            const float* base = cp + ((su - DEG) * N_CTRL + j) * 3;
            float cx = 0.f, cy = 0.f, cz = 0.f;
            #pragma unroll
            for (int a = 0; a < 4; ++a) {
                const float* q = base + a * (N_CTRL * 3);
                cx += B[a] * q[0];
                cy += B[a] * q[1];
                cz += B[a] * q[2];
            }
            s_curve[r][j] = make_float4(cx, cy, cz, 0.f);
        }
    }
    __syncthreads();

    // ---- batched pv loads: independent LDGs in flight ----
    float pvv[KITER];
    #pragma unroll
    for (int k = 0; k < KITER; ++k) {
        int p  = vstart + k * TPB + tid;
        int pc = p < vend ? p : vend - 1;
        pvv[k] = pv[pc];
    }

    // ---- main: closed-form v-basis, 8 rows per point, direct stores ----
    #pragma unroll
    for (int k = 0; k < KITER; ++k) {
        const int p = vstart + k * TPB + tid;
        if (p < vend) {
            const int sv = find_span(pvv[k]);
            float B[4];
            basis_v(pvv[k], sv, B);
            const int o = sv - DEG;
            #pragma unroll
            for (int r = 0; r < U_TILE; ++r) {
                if (r < nrows) {
                    const float4 c0 = s_curve[r][o + 0];
                    const float4 c1 = s_curve[r][o + 1];
                    const float4 c2 = s_curve[r][o + 2];
                    const float4 c3 = s_curve[r][o + 3];
                    float x = B[0] * c0.x + B[1] * c1.x + B[2] * c2.x + B[3] * c3.x;
                    float y = B[0] * c0.y + B[1] * c1.y + B[2] * c2.y + B[3] * c3.y;
                    float z = B[0] * c0.z + B[1] * c1.z + B[2] * c2.z + B[3] * c3.z;
                    float* dst = out + ((size_t)(u0 + r) * N_EVAL + p) * 3;
                    dst[0] = x;
                    dst[1] = y;
                    dst[2] = z;
                }
            }
        }
    }
}

extern "C" void kernel_launch(void* const* d_in, const int* in_sizes, int n_in,
                              void* d_out, int out_size) {
    const float* cp = (const float*)d_in[0];   // [64,64,3]
    const float* pu = (const float*)d_in[1];   // [2001]
    const float* pv = (const float*)d_in[2];   // [2001]
    float* out = (float*)d_out;

    dim3 grid(VSPLIT, (N_EVAL + U_TILE - 1) / U_TILE);   // (4, 251)
    nurbs_kernel<<<grid, TPB>>>(cp, pu, pv, out);
}